// round 14
// baseline (speedup 1.0000x reference)
#include <cuda_runtime.h>
#include <cuda_fp16.h>
#include <math.h>

#define Bb 128
#define Nn 128
#define Ee 300
#define Tt 255
#define CSZ 8
#define GPB 8
#define NT 512

__device__ float g_buffer[Bb * Nn * 256];
__device__ float g_stack [Bb * Nn * 256];
__device__ float g_loss  [Bb];

__device__ __forceinline__ float sigf(float x) { return 1.0f / (1.0f + expf(-x)); }

__device__ __forceinline__ unsigned smem_u32(const void* p) {
    unsigned a;
    asm("{ .reg .u64 t; cvta.to.shared.u64 t, %1; cvt.u32.u64 %0, t; }" : "=r"(a) : "l"(p));
    return a;
}
__device__ __forceinline__ void fence_cluster() {
    asm volatile("fence.acq_rel.cluster;" ::: "memory");
}
__device__ __forceinline__ void arrive_peer_rel(unsigned la, int p) {
    asm volatile("{ .reg .b32 ra; mapa.shared::cluster.u32 ra, %0, %1;"
                 " mbarrier.arrive.release.cluster.shared::cluster.b64 _, [ra]; }"
                 :: "r"(la), "r"(p) : "memory");
}
__device__ __forceinline__ void wait_parity_cluster(unsigned a, unsigned par) {
    asm volatile("{ .reg .pred P;\n"
                 "W_%=:\n"
                 " mbarrier.try_wait.parity.acquire.cluster.shared::cta.b64 P, [%0], %1, 0x989680;\n"
                 " @P bra D_%=;\n"
                 " bra W_%=;\n"
                 "D_%=:\n}"
                 :: "r"(a), "r"(par) : "memory");
}
__device__ __forceinline__ void st_remote_b64(unsigned la, int p, float x, float y) {
    unsigned long long v = ((unsigned long long)__float_as_uint(y) << 32)
                         | (unsigned long long)__float_as_uint(x);
    asm volatile("{ .reg .b32 ra; mapa.shared::cluster.u32 ra, %0, %1;"
                 " st.shared::cluster.b64 [ra], %2; }"
                 :: "r"(la), "r"(p), "l"(v) : "memory");
}
__device__ __forceinline__ void ldmatrix_x4(unsigned& a0, unsigned& a1,
                                            unsigned& a2, unsigned& a3, unsigned addr) {
    asm volatile("ldmatrix.sync.aligned.m8n8.x4.shared.b16 {%0,%1,%2,%3}, [%4];"
                 : "=r"(a0), "=r"(a1), "=r"(a2), "=r"(a3) : "r"(addr));
}
__device__ __forceinline__ void mma16816(float& d0, float& d1, float& d2, float& d3,
                                         unsigned a0, unsigned a1, unsigned a2, unsigned a3,
                                         unsigned b0, unsigned b1) {
    asm volatile("mma.sync.aligned.m16n8k16.row.col.f32.f16.f16.f32 "
                 "{%0,%1,%2,%3}, {%4,%5,%6,%7}, {%8,%9}, {%0,%1,%2,%3};"
                 : "+f"(d0), "+f"(d1), "+f"(d2), "+f"(d3)
                 : "r"(a0), "r"(a1), "r"(a2), "r"(a3), "r"(b0), "r"(b1));
}
__device__ __forceinline__ unsigned pack_h2(float a, float b) {
    __half2 h = __floats2half2_rn(a, b);
    return *(unsigned*)&h;
}

// ---------------------------------------------------------------------------
// Kernel 1: buffer[b,n,:] = embed_table[tokens[b,n]] @ W_proj
// ---------------------------------------------------------------------------
__global__ void __launch_bounds__(256) embed_kernel(
    const int*   __restrict__ tokens,
    const float* __restrict__ embed_table,
    const float* __restrict__ W_proj)
{
    __shared__ __align__(16) float se[16 * Ee];
    __shared__ int stok[16];
    const int blk = blockIdx.x;
    const int tid = threadIdx.x;

    if (tid < 16) stok[tid] = tokens[blk * 16 + tid];
    __syncthreads();
    for (int idx = tid; idx < 16 * Ee; idx += 256) {
        int j = idx / Ee, e = idx - j * Ee;
        se[idx] = embed_table[(size_t)stok[j] * Ee + e];
    }
    __syncthreads();

    const int col = tid;
    float acc[16];
#pragma unroll
    for (int j = 0; j < 16; j++) acc[j] = 0.0f;
    for (int e = 0; e < Ee; e += 4) {
        float w0 = W_proj[(e + 0) * 256 + col];
        float w1 = W_proj[(e + 1) * 256 + col];
        float w2 = W_proj[(e + 2) * 256 + col];
        float w3 = W_proj[(e + 3) * 256 + col];
#pragma unroll
        for (int j = 0; j < 16; j++) {
            float4 s = *(const float4*)&se[j * Ee + e];
            acc[j] += s.x * w0 + s.y * w1 + s.z * w2 + s.w * w3;
        }
    }
#pragma unroll
    for (int j = 0; j < 16; j++)
        g_buffer[(size_t)(blk * 16 + j) * 256 + col] = acc[j];
}

// ---------------------------------------------------------------------------
// Kernel 2: clustered scan; tensor-core GEMMs; 4-lane burst publish (28 arrives)
// ---------------------------------------------------------------------------
struct __align__(16) Smem {
    float h_s[2][GPB][128];
    float bt[GPB][256];
    float s1v[GPB][256];
    float s2v[GPB][256];
    float red_s[2][GPB][256];
    float pt[1664];                 // tracker 16*64 | tree at 1024: 10*64
    float c_s[GPB][16];
    float bias_lat[64];
    float bias_red[80];
    float wtrans[256];
    float btr[2];
    int   fin_ptr[GPB];
    unsigned long long mbar[2];     // [0]=hbar(28), [1]=sbar(28)
    __align__(16) __half xh[16 * 520];
    uint2 gbs[10 * 24 * 32];
    unsigned trbits[GPB][8];
    unsigned char sch_wp[Tt][GPB];
    unsigned char sch_bt[Tt + 1][GPB];
    signed char   sch_rf[Tt][GPB];
};

__global__ void __launch_bounds__(NT, 1) __cluster_dims__(CSZ, 1, 1)
spinn_seq(
    const int*   __restrict__ transitions,
    const float* __restrict__ W_buf,  const float* __restrict__ W_s1,
    const float* __restrict__ W_s2,   const float* __restrict__ W_lat,
    const float* __restrict__ b_lat,
    const float* __restrict__ W_trans,const float* __restrict__ b_trans,
    const float* __restrict__ W_left, const float* __restrict__ W_right,
    const float* __restrict__ W_track,const float* __restrict__ b_reduce,
    float* __restrict__ out_final)
{
    extern __shared__ char smraw[];
    Smem* sm = (Smem*)smraw;
    const int tid  = threadIdx.x;
    const int warp = tid >> 5;
    const int lane = tid & 31;
    const int r    = blockIdx.x & (CSZ - 1);
    const int b0   = blockIdx.x & ~(CSZ - 1);

    float*       stck = g_stack  + (size_t)b0 * Nn * 256;
    const float* buf  = g_buffer + (size_t)b0 * Nn * 256;

    // ---------------- init: tracker B fragments in registers ----------------
    unsigned tb0[16], tb1[16];
    {
        const int nt = warp & 7, kh = warp >> 3;
        const int cl = nt * 8 + (lane >> 2);
        const int G  = ((cl >> 4) << 7) + (r << 4) + (cl & 15);
#pragma unroll
        for (int mm = 0; mm < 16; mm++) {
            int kb = (kh * 16 + mm) * 16 + (lane & 3) * 2;
            float w00, w01, w10, w11;
            {
                int k = kb;
                w00 = (k < 128) ? W_buf[k * 512 + G] : (k < 256) ? W_s1[(k - 128) * 512 + G]
                    : (k < 384) ? W_s2[(k - 256) * 512 + G] : W_lat[(k - 384) * 512 + G];
                k = kb + 1;
                w01 = (k < 128) ? W_buf[k * 512 + G] : (k < 256) ? W_s1[(k - 128) * 512 + G]
                    : (k < 384) ? W_s2[(k - 256) * 512 + G] : W_lat[(k - 384) * 512 + G];
                k = kb + 8;
                w10 = (k < 128) ? W_buf[k * 512 + G] : (k < 256) ? W_s1[(k - 128) * 512 + G]
                    : (k < 384) ? W_s2[(k - 256) * 512 + G] : W_lat[(k - 384) * 512 + G];
                k = kb + 9;
                w11 = (k < 128) ? W_buf[k * 512 + G] : (k < 256) ? W_s1[(k - 128) * 512 + G]
                    : (k < 384) ? W_s2[(k - 256) * 512 + G] : W_lat[(k - 384) * 512 + G];
            }
            tb0[mm] = pack_h2(w00, w01);
            tb1[mm] = pack_h2(w10, w11);
        }
    }
    if (warp < 10) {
        const int cl = warp * 8 + (lane >> 2);
        const int G  = ((cl >> 4) << 7) + (r << 4) + (cl & 15);
        for (int mm = 0; mm < 24; mm++) {
            int m  = mm >> 3;
            int kk = (mm & 7) * 16 + (lane & 3) * 2;
            const float* W = (m == 0) ? W_left : (m == 1) ? W_right : W_track;
            uint2 v;
            v.x = pack_h2(W[kk * 640 + G],       W[(kk + 1) * 640 + G]);
            v.y = pack_h2(W[(kk + 8) * 640 + G], W[(kk + 9) * 640 + G]);
            sm->gbs[(warp * 24 + mm) * 32 + lane] = v;
        }
    }
    if (tid < 64) sm->bias_lat[tid] = b_lat[((tid >> 4) << 7) + (r << 4) + (tid & 15)];
    if (tid < 80) sm->bias_red[tid] = b_reduce[((tid >> 4) << 7) + (r << 4) + (tid & 15)];
    if (tid < 256) sm->wtrans[tid] = W_trans[tid];
    if (tid < 2) sm->btr[tid] = b_trans[tid];
    if (tid < 64) {
        int g = tid >> 3, w = tid & 7;
        unsigned bits = 0;
        for (int i = 0; i < 32; i++) {
            int tt = w * 32 + i;
            if (tt < Tt) bits |= (unsigned)(transitions[(b0 + g) * Tt + tt] & 1) << i;
        }
        sm->trbits[g][w] = bits;
    }
    for (int i = tid; i < 2 * GPB * 128; i += NT) ((float*)sm->h_s)[i] = 0.f;
    for (int i = tid; i < GPB * 16;  i += NT) ((float*)sm->c_s)[i] = 0.f;
    for (int i = tid; i < GPB * 256; i += NT) {
        ((float*)sm->s1v)[i] = 0.f;
        ((float*)sm->s2v)[i] = 0.f;
    }
    for (int i = tid; i < 2 * GPB * 256; i += NT) ((float*)sm->red_s)[i] = 0.f;
    for (int i = tid; i < 16 * 520; i += NT) sm->xh[i] = __float2half(0.f);
    for (int i = tid; i < GPB * 64; i += NT) {
        int b = i >> 6, q = (i & 63) * 4;
        *(float4*)&sm->bt[b][q] = *(const float4*)&buf[((size_t)b * Nn) * 256 + q];
    }
    if (tid == 0) {
        unsigned mb = smem_u32(&sm->mbar[0]);
        asm volatile("mbarrier.init.shared.b64 [%0], %1;" :: "r"(mb),   "r"(28) : "memory");
        asm volatile("mbarrier.init.shared.b64 [%0], %1;" :: "r"(mb+8), "r"(28) : "memory");
    }
    __syncthreads();

    if (tid < GPB) {
        const int g = tid;
        int p = 0, bp = 0;
        for (int t = 0; t < Tt; t++) {
            int trv = (sm->trbits[g][t >> 5] >> (t & 31)) & 1;
            int bi = (bp < Nn - 1) ? bp : (Nn - 1);
            sm->sch_bt[t][g] = (unsigned char)bi;
            int wp = trv ? ((p - 2 >= 0) ? p - 2 : 0) : p;
            if (wp > Nn - 1) wp = Nn - 1;
            sm->sch_wp[t][g] = (unsigned char)wp;
            sm->sch_rf[t][g] = (signed char)((trv && p >= 3) ? (p - 3) : -1);
            p  += trv ? -1 : 1;
            bp += trv ? 0 : 1;
        }
        sm->sch_bt[Tt][g] = sm->sch_bt[Tt - 1][g];
        int fin = (p - 1 >= 0) ? p - 1 : 0;
        sm->fin_ptr[g] = (fin > Nn - 1) ? Nn - 1 : fin;
    }
    __syncthreads();
    asm volatile("barrier.cluster.arrive.aligned;" ::: "memory");
    asm volatile("barrier.cluster.wait.aligned;"   ::: "memory");

    const unsigned hbar    = smem_u32(&sm->mbar[0]);
    const unsigned sbar    = hbar + 8;
    const unsigned hsbase  = smem_u32(&sm->h_s[0][0][0]);
    const unsigned redbase = smem_u32(&sm->red_s[0][0][0]);
    const unsigned xhbase  = smem_u32(&sm->xh[0]);

    const unsigned lrow  = lane & 15;
    const unsigned lcolb = (lane & 16) >> 1;
    const unsigned abase = xhbase + (lrow * 520u + lcolb) * 2u;

    const int rb_ = tid >> 6;               // rename batch owner
    const int rd  = (tid & 63) * 4;         // 4-float chunk of 256
    // publishers: warps 9..15 -> 7 peers; lanes 0..3 store + arrive
    const int isPub = (warp >= 9);
    const int pw    = warp - 9;
    const int peer  = pw + (pw >= r ? 1 : 0);
    const int isPubLane = isPub && (lane < 4);

    const float4 z4 = make_float4(0.f, 0.f, 0.f, 0.f);
    float4 rfa = z4, bna = z4;
    float loss_reg = 0.f;
    int sp = 0;
    int prevAny = 0;

    for (int t = 0; t < Tt; t++) {
        const int w5 = t >> 5, b5 = t & 31;
        const int rb = t & 1, wbuf = 1 - rb;

        unsigned anyr = 0;
#pragma unroll
        for (int g = 0; g < GPB; g++) anyr |= (sm->trbits[g][w5] >> b5) & 1u;

        // ======== P0 (fused): sbar wait + rename + xh fill + stack write + prefetch
        const int slot = sp & 1;
        if (prevAny) { wait_parity_cluster(sbar, slot); sp++; }
        {
            float4 bt_v = *(const float4*)&sm->bt[rb_][rd];
            float4 s1_v = *(const float4*)&sm->s1v[rb_][rd];
            float4 s2_v = *(const float4*)&sm->s2v[rb_][rd];
            if (t > 0) {
                if ((sm->trbits[rb_][(t - 1) >> 5] >> ((t - 1) & 31)) & 1) {
                    s1_v = *(const float4*)&sm->red_s[slot][rb_][rd];
                    s2_v = rfa;
                } else {
                    s2_v = s1_v; s1_v = bt_v; bt_v = bna;
                }
                *(float4*)&sm->bt[rb_][rd]  = bt_v;
                *(float4*)&sm->s1v[rb_][rd] = s1_v;
                *(float4*)&sm->s2v[rb_][rd] = s2_v;
            }
            if (rd < 128) {   // fp16 staging for mma A (h-halves only)
                uint2 v;
                v.x = pack_h2(bt_v.x, bt_v.y); v.y = pack_h2(bt_v.z, bt_v.w);
                *(uint2*)&sm->xh[rb_ * 520 + rd] = v;
                v.x = pack_h2(s1_v.x, s1_v.y); v.y = pack_h2(s1_v.z, s1_v.w);
                *(uint2*)&sm->xh[rb_ * 520 + 128 + rd] = v;
                v.x = pack_h2(s2_v.x, s2_v.y); v.y = pack_h2(s2_v.z, s2_v.w);
                *(uint2*)&sm->xh[rb_ * 520 + 256 + rd] = v;
            }
            // shift stack write: this CTA's 32-col slice
            if ((((sm->trbits[rb_][w5] >> b5) & 1) == 0) && ((rd >> 5) == r)) {
                const int wp = sm->sch_wp[t][rb_];
                __stcg((float4*)&stck[((size_t)rb_ * Nn + wp) * 256 + rd], bt_v);
            }
            // prefetch for next step
            int nbt = sm->sch_bt[t + 1][rb_];
            bna = __ldg((const float4*)&buf[((size_t)rb_ * Nn + nbt) * 256 + rd]);
            int rfi = sm->sch_rf[t][rb_];
            rfa = (rfi >= 0)
                ? __ldcg((const float4*)&stck[((size_t)rb_ * Nn + rfi) * 256 + rd])
                : z4;
        }
        __syncthreads();   // SYNC_A

        // ======== P1: tracker mma (16 warps) + lazy loss (warp 15)
        {
            float d0 = 0.f, d1 = 0.f, d2 = 0.f, d3 = 0.f;
#pragma unroll
            for (int mm = 0; mm < 16; mm++) {
                const unsigned k0 = ((unsigned)((warp >> 3) * 16 + mm)) * 16u;
                unsigned a0, a1, a2, a3;
                ldmatrix_x4(a0, a1, a2, a3, abase + k0 * 2u);
                mma16816(d0, d1, d2, d3, a0, a1, a2, a3, tb0[mm], tb1[mm]);
            }
            const int row = lane >> 2, cc = (lane & 3) * 2;
            sm->pt[warp * 64 + row * 8 + cc]     = d0;
            sm->pt[warp * 64 + row * 8 + cc + 1] = d1;
        }
        if (t > 0 && warp == 15) {
            float p0 = 0.f, p1 = 0.f;
#pragma unroll
            for (int m = 0; m < 4; m++) {
                int j = lane + 32 * m;
                float h = sm->h_s[rb][r][j];
                p0 += h * sm->wtrans[2 * j];
                p1 += h * sm->wtrans[2 * j + 1];
            }
#pragma unroll
            for (int off = 16; off > 0; off >>= 1) {
                p0 += __shfl_xor_sync(0xffffffffu, p0, off);
                p1 += __shfl_xor_sync(0xffffffffu, p1, off);
            }
            if (lane == 0) {
                float l0 = p0 + sm->btr[0], l1 = p1 + sm->btr[1];
                float m = fmaxf(l0, l1);
                float lse = m + logf(expf(l0 - m) + expf(l1 - m));
                int trp = (sm->trbits[r][(t - 1) >> 5] >> ((t - 1) & 31)) & 1;
                loss_reg += lse - ((trp == 0) ? l0 : l1);
            }
        }
        __syncthreads();   // SYNC_B

        // ======== P2: cell update -> h_s[wbuf], c_s
        if (tid < 128) {
            const int jj = tid >> 3, b = tid & 7;
            float ga[4];
#pragma unroll
            for (int g = 0; g < 4; g++) {
                int c = g * 16 + jj;
                int u0 = (c >> 3), u1 = 8 + (c >> 3), o = b * 8 + (c & 7);
                float v = sm->pt[u0 * 64 + o] + sm->pt[u1 * 64 + o];
                if (t > 0) v += sm->bias_lat[c];
                ga[g] = v;
            }
            float cn = sigf(ga[2]) * sm->c_s[b][jj] + sigf(ga[1]) * tanhf(ga[0]);
            float hn = sigf(ga[3]) * tanhf(cn);
            sm->c_s[b][jj] = cn;
            sm->h_s[wbuf][b][(r << 4) + jj] = hn;
        }
        __syncthreads();   // SYNC_C

        // ======== P3: h publish (4-lane bursts) || tree L/R mma (warps 0-9)
        float e0 = 0.f, e1 = 0.f, e2 = 0.f, e3 = 0.f;
        if (isPubLane) {
#pragma unroll
            for (int i = 0; i < 16; i++) {
                int u = lane * 16 + i;                // 0..63 : 64 b64 = 512B
                int b = u >> 3, o = (u & 7) * 2;
                float2 hv = *(const float2*)&sm->h_s[wbuf][b][(r << 4) + o];
                unsigned la = hsbase + (unsigned)(((wbuf * GPB + b) * 128 + (r << 4) + o) * 4);
                st_remote_b64(la, peer, hv.x, hv.y);
            }
            arrive_peer_rel(hbar, peer);
        }
        if (anyr && warp < 10) {
#pragma unroll
            for (int mm = 0; mm < 16; mm++) {
                const unsigned k0 = (unsigned)(((mm >> 3) ? 128 : 256) + (mm & 7) * 16);
                unsigned a0, a1, a2, a3;
                ldmatrix_x4(a0, a1, a2, a3, abase + k0 * 2u);
                uint2 bfr = sm->gbs[(warp * 24 + mm) * 32 + lane];
                mma16816(e0, e1, e2, e3, a0, a1, a2, a3, bfr.x, bfr.y);
            }
        }

        // ======== P4: warps 10-15 wait hbar(t) + fill xh h-cols
        if (warp >= 10) {
            wait_parity_cluster(hbar, t & 1);
            for (int i = tid - 320; i < 512; i += 192) {
                int b = i >> 6, o = (i & 63) * 2;
                __half2 hv = __floats2half2_rn(sm->h_s[wbuf][b][o], sm->h_s[wbuf][b][o + 1]);
                *(__half2*)&sm->xh[b * 520 + 384 + o] = hv;
            }
        }
        __syncthreads();   // SYNC_D

        if (anyr) {
            // ---- P5: tree m2 (track) mma + store ----
            if (warp < 10) {
#pragma unroll
                for (int mm = 16; mm < 24; mm++) {
                    const unsigned k0 = (unsigned)(384 + (mm & 7) * 16);
                    unsigned a0, a1, a2, a3;
                    ldmatrix_x4(a0, a1, a2, a3, abase + k0 * 2u);
                    uint2 bfr = sm->gbs[(warp * 24 + mm) * 32 + lane];
                    mma16816(e0, e1, e2, e3, a0, a1, a2, a3, bfr.x, bfr.y);
                }
                const int row = lane >> 2, cc = (lane & 3) * 2;
                sm->pt[1024 + warp * 64 + row * 8 + cc]     = e0;
                sm->pt[1024 + warp * 64 + row * 8 + cc + 1] = e1;
            }
            __syncthreads();   // SYNC_E

            // ---- P6: compose -> red_s + stack stcg ----
            const int slotW = sp & 1;
            if (tid < 128) {
                const int jj = tid >> 3, b = tid & 7;
                if ((sm->trbits[b][w5] >> b5) & 1) {
                    const int j = (r << 4) + jj;
                    float gg[5];
#pragma unroll
                    for (int g = 0; g < 5; g++) {
                        int c = g * 16 + jj;
                        gg[g] = sm->pt[1024 + (c >> 3) * 64 + b * 8 + (c & 7)]
                              + sm->bias_red[c];
                    }
                    float cn = tanhf(gg[0]) * sigf(gg[1])
                             + sigf(gg[2]) * sm->s2v[b][128 + j]
                             + sigf(gg[3]) * sm->s1v[b][128 + j];
                    float v1 = cn;
                    float v0 = sigf(gg[4]) * tanhf(cn);
                    const int wp = sm->sch_wp[t][b];
                    __stcg(&stck[((size_t)b * Nn + wp) * 256 + j], v0);
                    __stcg(&stck[((size_t)b * Nn + wp) * 256 + 128 + j], v1);
                    sm->red_s[slotW][b][j]       = v0;
                    sm->red_s[slotW][b][128 + j] = v1;
                }
            }
            __syncthreads();   // SYNC_F

            // ---- P7: red publish (4-lane bursts) + sbar arrive ----
            if (isPubLane) {
#pragma unroll
                for (int i = 0; i < 32; i++) {
                    int u = lane * 32 + i;            // 0..127 : 128 b64 = 1KB
                    int half = u >> 6, b = (u >> 3) & 7, o = (u & 7) * 2;
                    float2 rv = *(const float2*)&sm->red_s[slotW][b][half * 128 + (r << 4) + o];
                    unsigned la = redbase + (unsigned)(((slotW * GPB + b) * 256
                                   + half * 128 + (r << 4) + o) * 4);
                    st_remote_b64(la, peer, rv.x, rv.y);
                }
                arrive_peer_rel(sbar, peer);
            }
        }
        prevAny = anyr;
    }

    fence_cluster();
    asm volatile("barrier.cluster.arrive.aligned;" ::: "memory");
    asm volatile("barrier.cluster.wait.aligned;"   ::: "memory");

    // final step's loss
    if (warp == 15) {
        const int wb_last = 1 - ((Tt - 1) & 1);
        float p0 = 0.f, p1 = 0.f;
#pragma unroll
        for (int m = 0; m < 4; m++) {
            int j = lane + 32 * m;
            float h = sm->h_s[wb_last][r][j];
            p0 += h * sm->wtrans[2 * j];
            p1 += h * sm->wtrans[2 * j + 1];
        }
#pragma unroll
        for (int off = 16; off > 0; off >>= 1) {
            p0 += __shfl_xor_sync(0xffffffffu, p0, off);
            p1 += __shfl_xor_sync(0xffffffffu, p1, off);
        }
        if (lane == 0) {
            float l0 = p0 + sm->btr[0], l1 = p1 + sm->btr[1];
            float m = fmaxf(l0, l1);
            float lse = m + logf(expf(l0 - m) + expf(l1 - m));
            int trp = (sm->trbits[r][(Tt - 1) >> 5] >> ((Tt - 1) & 31)) & 1;
            loss_reg += lse - ((trp == 0) ? l0 : l1);
            g_loss[b0 + r] = loss_reg;
        }
    }

    if (tid < 64) {
        int fin = sm->fin_ptr[r];
        float4 v = __ldcg((const float4*)&stck[((size_t)r * Nn + fin) * 256 + tid * 4]);
        *(float4*)&out_final[(size_t)(b0 + r) * 256 + tid * 4] = v;
    }
}

// ---------------------------------------------------------------------------
// Kernel 3: loss reduction
// ---------------------------------------------------------------------------
__global__ void loss_kernel(float* __restrict__ out, int loss_idx)
{
    __shared__ float sl[128];
    int tid = threadIdx.x;
    sl[tid] = g_loss[tid];
    __syncthreads();
    for (int off = 64; off > 0; off >>= 1) {
        if (tid < off) sl[tid] += sl[tid + off];
        __syncthreads();
    }
    if (tid == 0) out[loss_idx] = sl[0] / (float)(Tt * Bb);
}

// ---------------------------------------------------------------------------
extern "C" void kernel_launch(void* const* d_in, const int* in_sizes, int n_in,
                              void* d_out, int out_size)
{
    const int*   tokens      = (const int*)  d_in[0];
    const int*   transitions = (const int*)  d_in[1];
    const float* embed_table = (const float*)d_in[2];
    const float* W_proj      = (const float*)d_in[3];
    const float* W_buf       = (const float*)d_in[4];
    const float* W_s1        = (const float*)d_in[5];
    const float* W_s2        = (const float*)d_in[6];
    const float* W_lat       = (const float*)d_in[7];
    const float* b_lat       = (const float*)d_in[8];
    const float* W_trans     = (const float*)d_in[9];
    const float* b_trans     = (const float*)d_in[10];
    const float* W_left      = (const float*)d_in[11];
    const float* W_right     = (const float*)d_in[12];
    const float* W_track     = (const float*)d_in[13];
    const float* b_reduce    = (const float*)d_in[14];
    float* out = (float*)d_out;

    static bool attr_done = false;
    if (!attr_done) {
        cudaFuncSetAttribute(spinn_seq,
                             cudaFuncAttributeMaxDynamicSharedMemorySize,
                             (int)sizeof(Smem));
        attr_done = true;
    }

    embed_kernel<<<(Bb * Nn) / 16, 256>>>(tokens, embed_table, W_proj);
    spinn_seq<<<Bb, NT, sizeof(Smem)>>>(transitions,
                                        W_buf, W_s1, W_s2, W_lat, b_lat,
                                        W_trans, b_trans,
                                        W_left, W_right, W_track, b_reduce,
                                        out);
    loss_kernel<<<1, 128>>>(out, out_size - 1);
}

// round 15
// speedup vs baseline: 1.1722x; 1.1722x over previous
#include <cuda_runtime.h>
#include <cuda_fp16.h>
#include <math.h>

#define Bb 128
#define Nn 128
#define Ee 300
#define Tt 255
#define CSZ 8
#define GPB 8
#define NT 512

__device__ float g_buffer[Bb * Nn * 256];
__device__ float g_stack [Bb * Nn * 256];
__device__ float g_loss  [Bb];

__device__ __forceinline__ float sigf(float x) { return 1.0f / (1.0f + expf(-x)); }

__device__ __forceinline__ unsigned smem_u32(const void* p) {
    unsigned a;
    asm("{ .reg .u64 t; cvta.to.shared.u64 t, %1; cvt.u32.u64 %0, t; }" : "=r"(a) : "l"(p));
    return a;
}
__device__ __forceinline__ void fence_cluster() {
    asm volatile("fence.acq_rel.cluster;" ::: "memory");
}
__device__ __forceinline__ void arrive_peer_rel(unsigned la, int p) {
    asm volatile("{ .reg .b32 ra; mapa.shared::cluster.u32 ra, %0, %1;"
                 " mbarrier.arrive.release.cluster.shared::cluster.b64 _, [ra]; }"
                 :: "r"(la), "r"(p) : "memory");
}
__device__ __forceinline__ void wait_parity_cluster(unsigned a, unsigned par) {
    asm volatile("{ .reg .pred P;\n"
                 "W_%=:\n"
                 " mbarrier.try_wait.parity.acquire.cluster.shared::cta.b64 P, [%0], %1, 0x989680;\n"
                 " @P bra D_%=;\n"
                 " bra W_%=;\n"
                 "D_%=:\n}"
                 :: "r"(a), "r"(par) : "memory");
}
__device__ __forceinline__ void st_remote_b64(unsigned la, int p, float x, float y) {
    unsigned long long v = ((unsigned long long)__float_as_uint(y) << 32)
                         | (unsigned long long)__float_as_uint(x);
    asm volatile("{ .reg .b32 ra; mapa.shared::cluster.u32 ra, %0, %1;"
                 " st.shared::cluster.b64 [ra], %2; }"
                 :: "r"(la), "r"(p), "l"(v) : "memory");
}
__device__ __forceinline__ void ldmatrix_x4(unsigned& a0, unsigned& a1,
                                            unsigned& a2, unsigned& a3, unsigned addr) {
    asm volatile("ldmatrix.sync.aligned.m8n8.x4.shared.b16 {%0,%1,%2,%3}, [%4];"
                 : "=r"(a0), "=r"(a1), "=r"(a2), "=r"(a3) : "r"(addr));
}
__device__ __forceinline__ void mma16816(float& d0, float& d1, float& d2, float& d3,
                                         unsigned a0, unsigned a1, unsigned a2, unsigned a3,
                                         unsigned b0, unsigned b1) {
    asm volatile("mma.sync.aligned.m16n8k16.row.col.f32.f16.f16.f32 "
                 "{%0,%1,%2,%3}, {%4,%5,%6,%7}, {%8,%9}, {%0,%1,%2,%3};"
                 : "+f"(d0), "+f"(d1), "+f"(d2), "+f"(d3)
                 : "r"(a0), "r"(a1), "r"(a2), "r"(a3), "r"(b0), "r"(b1));
}
__device__ __forceinline__ unsigned pack_h2(float a, float b) {
    __half2 h = __floats2half2_rn(a, b);
    return *(unsigned*)&h;
}

// ---------------------------------------------------------------------------
// Kernel 1: buffer[b,n,:] = embed_table[tokens[b,n]] @ W_proj
// 8 tokens/block -> 2048 blocks, 2 CTAs/SM, halved dependency chains.
// ---------------------------------------------------------------------------
#define ETOK 8
__global__ void __launch_bounds__(256) embed_kernel(
    const int*   __restrict__ tokens,
    const float* __restrict__ embed_table,
    const float* __restrict__ W_proj)
{
    __shared__ __align__(16) float se[ETOK * Ee];
    __shared__ int stok[ETOK];
    const int blk = blockIdx.x;
    const int tid = threadIdx.x;

    if (tid < ETOK) stok[tid] = tokens[blk * ETOK + tid];
    __syncthreads();
    for (int idx = tid; idx < ETOK * Ee; idx += 256) {
        int j = idx / Ee, e = idx - j * Ee;
        se[idx] = embed_table[(size_t)stok[j] * Ee + e];
    }
    __syncthreads();

    const int col = tid;
    float acc[ETOK];
#pragma unroll
    for (int j = 0; j < ETOK; j++) acc[j] = 0.0f;
    for (int e = 0; e < Ee; e += 4) {
        float w0 = W_proj[(e + 0) * 256 + col];
        float w1 = W_proj[(e + 1) * 256 + col];
        float w2 = W_proj[(e + 2) * 256 + col];
        float w3 = W_proj[(e + 3) * 256 + col];
#pragma unroll
        for (int j = 0; j < ETOK; j++) {
            float4 s = *(const float4*)&se[j * Ee + e];
            acc[j] += s.x * w0 + s.y * w1 + s.z * w2 + s.w * w3;
        }
    }
#pragma unroll
    for (int j = 0; j < ETOK; j++)
        g_buffer[(size_t)(blk * ETOK + j) * 256 + col] = acc[j];
}

// ---------------------------------------------------------------------------
// Kernel 2: clustered scan, tensor-core GEMMs, R10 comms + fused P0
// ---------------------------------------------------------------------------
struct __align__(16) Smem {
    float h_s[2][GPB][128];
    float bt[GPB][256];
    float s1v[GPB][256];
    float s2v[GPB][256];
    float red_s[2][GPB][256];
    float pt[1664];                 // tracker 16*64 | tree at 1024: 10*64
    float c_s[GPB][16];
    float bias_lat[64];
    float bias_red[80];
    float wtrans[256];
    float btr[2];
    int   fin_ptr[GPB];
    unsigned long long mbar[2];     // [0]=hbar, [1]=sbar (count 224)
    __align__(16) __half xh[16 * 520];
    uint2 gbs[10 * 24 * 32];
    unsigned trbits[GPB][8];
    unsigned char sch_wp[Tt][GPB];
    unsigned char sch_bt[Tt + 1][GPB];
    signed char   sch_rf[Tt][GPB];
};

__global__ void __launch_bounds__(NT, 1) __cluster_dims__(CSZ, 1, 1)
spinn_seq(
    const int*   __restrict__ transitions,
    const float* __restrict__ W_buf,  const float* __restrict__ W_s1,
    const float* __restrict__ W_s2,   const float* __restrict__ W_lat,
    const float* __restrict__ b_lat,
    const float* __restrict__ W_trans,const float* __restrict__ b_trans,
    const float* __restrict__ W_left, const float* __restrict__ W_right,
    const float* __restrict__ W_track,const float* __restrict__ b_reduce,
    float* __restrict__ out_final)
{
    extern __shared__ char smraw[];
    Smem* sm = (Smem*)smraw;
    const int tid  = threadIdx.x;
    const int warp = tid >> 5;
    const int lane = tid & 31;
    const int r    = blockIdx.x & (CSZ - 1);
    const int b0   = blockIdx.x & ~(CSZ - 1);

    float*       stck = g_stack  + (size_t)b0 * Nn * 256;
    const float* buf  = g_buffer + (size_t)b0 * Nn * 256;

    // ---------------- init: tracker B fragments in registers ----------------
    unsigned tb0[16], tb1[16];
    {
        const int nt = warp & 7, kh = warp >> 3;
        const int cl = nt * 8 + (lane >> 2);
        const int G  = ((cl >> 4) << 7) + (r << 4) + (cl & 15);
#pragma unroll
        for (int mm = 0; mm < 16; mm++) {
            int kb = (kh * 16 + mm) * 16 + (lane & 3) * 2;
            float w00, w01, w10, w11;
            {
                int k = kb;
                w00 = (k < 128) ? W_buf[k * 512 + G] : (k < 256) ? W_s1[(k - 128) * 512 + G]
                    : (k < 384) ? W_s2[(k - 256) * 512 + G] : W_lat[(k - 384) * 512 + G];
                k = kb + 1;
                w01 = (k < 128) ? W_buf[k * 512 + G] : (k < 256) ? W_s1[(k - 128) * 512 + G]
                    : (k < 384) ? W_s2[(k - 256) * 512 + G] : W_lat[(k - 384) * 512 + G];
                k = kb + 8;
                w10 = (k < 128) ? W_buf[k * 512 + G] : (k < 256) ? W_s1[(k - 128) * 512 + G]
                    : (k < 384) ? W_s2[(k - 256) * 512 + G] : W_lat[(k - 384) * 512 + G];
                k = kb + 9;
                w11 = (k < 128) ? W_buf[k * 512 + G] : (k < 256) ? W_s1[(k - 128) * 512 + G]
                    : (k < 384) ? W_s2[(k - 256) * 512 + G] : W_lat[(k - 384) * 512 + G];
            }
            tb0[mm] = pack_h2(w00, w01);
            tb1[mm] = pack_h2(w10, w11);
        }
    }
    if (warp < 10) {
        const int cl = warp * 8 + (lane >> 2);
        const int G  = ((cl >> 4) << 7) + (r << 4) + (cl & 15);
        for (int mm = 0; mm < 24; mm++) {
            int m  = mm >> 3;
            int kk = (mm & 7) * 16 + (lane & 3) * 2;
            const float* W = (m == 0) ? W_left : (m == 1) ? W_right : W_track;
            uint2 v;
            v.x = pack_h2(W[kk * 640 + G],       W[(kk + 1) * 640 + G]);
            v.y = pack_h2(W[(kk + 8) * 640 + G], W[(kk + 9) * 640 + G]);
            sm->gbs[(warp * 24 + mm) * 32 + lane] = v;
        }
    }
    if (tid < 64) sm->bias_lat[tid] = b_lat[((tid >> 4) << 7) + (r << 4) + (tid & 15)];
    if (tid < 80) sm->bias_red[tid] = b_reduce[((tid >> 4) << 7) + (r << 4) + (tid & 15)];
    if (tid < 256) sm->wtrans[tid] = W_trans[tid];
    if (tid < 2) sm->btr[tid] = b_trans[tid];
    if (tid < 64) {
        int g = tid >> 3, w = tid & 7;
        unsigned bits = 0;
        for (int i = 0; i < 32; i++) {
            int tt = w * 32 + i;
            if (tt < Tt) bits |= (unsigned)(transitions[(b0 + g) * Tt + tt] & 1) << i;
        }
        sm->trbits[g][w] = bits;
    }
    for (int i = tid; i < 2 * GPB * 128; i += NT) ((float*)sm->h_s)[i] = 0.f;
    for (int i = tid; i < GPB * 16;  i += NT) ((float*)sm->c_s)[i] = 0.f;
    for (int i = tid; i < GPB * 256; i += NT) {
        ((float*)sm->s1v)[i] = 0.f;
        ((float*)sm->s2v)[i] = 0.f;
    }
    for (int i = tid; i < 2 * GPB * 256; i += NT) ((float*)sm->red_s)[i] = 0.f;
    for (int i = tid; i < 16 * 520; i += NT) sm->xh[i] = __float2half(0.f);
    for (int i = tid; i < GPB * 64; i += NT) {
        int b = i >> 6, q = (i & 63) * 4;
        *(float4*)&sm->bt[b][q] = *(const float4*)&buf[((size_t)b * Nn) * 256 + q];
    }
    if (tid == 0) {
        unsigned mb = smem_u32(&sm->mbar[0]);
        asm volatile("mbarrier.init.shared.b64 [%0], %1;" :: "r"(mb),   "r"(224) : "memory");
        asm volatile("mbarrier.init.shared.b64 [%0], %1;" :: "r"(mb+8), "r"(224) : "memory");
    }
    __syncthreads();

    if (tid < GPB) {
        const int g = tid;
        int p = 0, bp = 0;
        for (int t = 0; t < Tt; t++) {
            int trv = (sm->trbits[g][t >> 5] >> (t & 31)) & 1;
            int bi = (bp < Nn - 1) ? bp : (Nn - 1);
            sm->sch_bt[t][g] = (unsigned char)bi;
            int wp = trv ? ((p - 2 >= 0) ? p - 2 : 0) : p;
            if (wp > Nn - 1) wp = Nn - 1;
            sm->sch_wp[t][g] = (unsigned char)wp;
            sm->sch_rf[t][g] = (signed char)((trv && p >= 3) ? (p - 3) : -1);
            p  += trv ? -1 : 1;
            bp += trv ? 0 : 1;
        }
        sm->sch_bt[Tt][g] = sm->sch_bt[Tt - 1][g];
        int fin = (p - 1 >= 0) ? p - 1 : 0;
        sm->fin_ptr[g] = (fin > Nn - 1) ? Nn - 1 : fin;
    }
    __syncthreads();
    asm volatile("barrier.cluster.arrive.aligned;" ::: "memory");
    asm volatile("barrier.cluster.wait.aligned;"   ::: "memory");

    const unsigned hbar    = smem_u32(&sm->mbar[0]);
    const unsigned sbar    = hbar + 8;
    const unsigned hsbase  = smem_u32(&sm->h_s[0][0][0]);
    const unsigned redbase = smem_u32(&sm->red_s[0][0][0]);
    const unsigned xhbase  = smem_u32(&sm->xh[0]);

    const unsigned lrow  = lane & 15;
    const unsigned lcolb = (lane & 16) >> 1;
    const unsigned abase = xhbase + (lrow * 520u + lcolb) * 2u;

    const int rb_ = tid >> 6;               // rename batch owner
    const int rd  = (tid & 63) * 4;         // 4-float chunk of 256
    // publishers: warps 9..15 -> 7 peers (224 arrivals/step; validated optimum)
    const int isPub = (warp >= 9);
    const int pw    = warp - 9;
    const int peer  = pw + (pw >= r ? 1 : 0);

    const float4 z4 = make_float4(0.f, 0.f, 0.f, 0.f);
    float4 rfa = z4, bna = z4;
    float loss_reg = 0.f;
    int sp = 0;
    int prevAny = 0;

    for (int t = 0; t < Tt; t++) {
        const int w5 = t >> 5, b5 = t & 31;
        const int rb = t & 1, wbuf = 1 - rb;

        unsigned anyr = 0;
#pragma unroll
        for (int g = 0; g < GPB; g++) anyr |= (sm->trbits[g][w5] >> b5) & 1u;

        // ======== P0 (fused): sbar wait + rename + xh fill + stack write + prefetch
        const int slot = sp & 1;
        if (prevAny) { wait_parity_cluster(sbar, slot); sp++; }
        {
            float4 bt_v = *(const float4*)&sm->bt[rb_][rd];
            float4 s1_v = *(const float4*)&sm->s1v[rb_][rd];
            float4 s2_v = *(const float4*)&sm->s2v[rb_][rd];
            if (t > 0) {
                if ((sm->trbits[rb_][(t - 1) >> 5] >> ((t - 1) & 31)) & 1) {
                    s1_v = *(const float4*)&sm->red_s[slot][rb_][rd];
                    s2_v = rfa;
                } else {
                    s2_v = s1_v; s1_v = bt_v; bt_v = bna;
                }
                *(float4*)&sm->bt[rb_][rd]  = bt_v;
                *(float4*)&sm->s1v[rb_][rd] = s1_v;
                *(float4*)&sm->s2v[rb_][rd] = s2_v;
            }
            if (rd < 128) {   // fp16 staging for mma A (h-halves only)
                uint2 v;
                v.x = pack_h2(bt_v.x, bt_v.y); v.y = pack_h2(bt_v.z, bt_v.w);
                *(uint2*)&sm->xh[rb_ * 520 + rd] = v;
                v.x = pack_h2(s1_v.x, s1_v.y); v.y = pack_h2(s1_v.z, s1_v.w);
                *(uint2*)&sm->xh[rb_ * 520 + 128 + rd] = v;
                v.x = pack_h2(s2_v.x, s2_v.y); v.y = pack_h2(s2_v.z, s2_v.w);
                *(uint2*)&sm->xh[rb_ * 520 + 256 + rd] = v;
            }
            // shift stack write: this CTA's 32-col slice
            if ((((sm->trbits[rb_][w5] >> b5) & 1) == 0) && ((rd >> 5) == r)) {
                const int wp = sm->sch_wp[t][rb_];
                __stcg((float4*)&stck[((size_t)rb_ * Nn + wp) * 256 + rd], bt_v);
            }
            // prefetch for next step
            int nbt = sm->sch_bt[t + 1][rb_];
            bna = __ldg((const float4*)&buf[((size_t)rb_ * Nn + nbt) * 256 + rd]);
            int rfi = sm->sch_rf[t][rb_];
            rfa = (rfi >= 0)
                ? __ldcg((const float4*)&stck[((size_t)rb_ * Nn + rfi) * 256 + rd])
                : z4;
        }
        __syncthreads();   // SYNC_A

        // ======== P1: tracker mma (16 warps) + lazy loss (warp 15)
        {
            float d0 = 0.f, d1 = 0.f, d2 = 0.f, d3 = 0.f;
#pragma unroll
            for (int mm = 0; mm < 16; mm++) {
                const unsigned k0 = ((unsigned)((warp >> 3) * 16 + mm)) * 16u;
                unsigned a0, a1, a2, a3;
                ldmatrix_x4(a0, a1, a2, a3, abase + k0 * 2u);
                mma16816(d0, d1, d2, d3, a0, a1, a2, a3, tb0[mm], tb1[mm]);
            }
            const int row = lane >> 2, cc = (lane & 3) * 2;
            sm->pt[warp * 64 + row * 8 + cc]     = d0;
            sm->pt[warp * 64 + row * 8 + cc + 1] = d1;
        }
        if (t > 0 && warp == 15) {
            float p0 = 0.f, p1 = 0.f;
#pragma unroll
            for (int m = 0; m < 4; m++) {
                int j = lane + 32 * m;
                float h = sm->h_s[rb][r][j];
                p0 += h * sm->wtrans[2 * j];
                p1 += h * sm->wtrans[2 * j + 1];
            }
#pragma unroll
            for (int off = 16; off > 0; off >>= 1) {
                p0 += __shfl_xor_sync(0xffffffffu, p0, off);
                p1 += __shfl_xor_sync(0xffffffffu, p1, off);
            }
            if (lane == 0) {
                float l0 = p0 + sm->btr[0], l1 = p1 + sm->btr[1];
                float m = fmaxf(l0, l1);
                float lse = m + logf(expf(l0 - m) + expf(l1 - m));
                int trp = (sm->trbits[r][(t - 1) >> 5] >> ((t - 1) & 31)) & 1;
                loss_reg += lse - ((trp == 0) ? l0 : l1);
            }
        }
        __syncthreads();   // SYNC_B

        // ======== P2: cell update -> h_s[wbuf], c_s
        if (tid < 128) {
            const int jj = tid >> 3, b = tid & 7;
            float ga[4];
#pragma unroll
            for (int g = 0; g < 4; g++) {
                int c = g * 16 + jj;
                int u0 = (c >> 3), u1 = 8 + (c >> 3), o = b * 8 + (c & 7);
                float v = sm->pt[u0 * 64 + o] + sm->pt[u1 * 64 + o];
                if (t > 0) v += sm->bias_lat[c];
                ga[g] = v;
            }
            float cn = sigf(ga[2]) * sm->c_s[b][jj] + sigf(ga[1]) * tanhf(ga[0]);
            float hn = sigf(ga[3]) * tanhf(cn);
            sm->c_s[b][jj] = cn;
            sm->h_s[wbuf][b][(r << 4) + jj] = hn;
        }
        __syncthreads();   // SYNC_C

        // ======== P3: h publish (warps 9-15) || tree L/R mma (warps 0-9)
        float e0 = 0.f, e1 = 0.f, e2 = 0.f, e3 = 0.f;
        if (isPub) {
#pragma unroll
            for (int rr = 0; rr < 2; rr++) {
                int u = lane + rr * 32;
                int b = u >> 3, o = (u & 7) * 2;
                float2 hv = *(const float2*)&sm->h_s[wbuf][b][(r << 4) + o];
                unsigned la = hsbase + (unsigned)(((wbuf * GPB + b) * 128 + (r << 4) + o) * 4);
                st_remote_b64(la, peer, hv.x, hv.y);
            }
            arrive_peer_rel(hbar, peer);
        }
        if (anyr && warp < 10) {
#pragma unroll
            for (int mm = 0; mm < 16; mm++) {
                const unsigned k0 = (unsigned)(((mm >> 3) ? 128 : 256) + (mm & 7) * 16);
                unsigned a0, a1, a2, a3;
                ldmatrix_x4(a0, a1, a2, a3, abase + k0 * 2u);
                uint2 bfr = sm->gbs[(warp * 24 + mm) * 32 + lane];
                mma16816(e0, e1, e2, e3, a0, a1, a2, a3, bfr.x, bfr.y);
            }
        }

        // ======== P4: warps 10-15 wait hbar(t) + fill xh h-cols
        if (warp >= 10) {
            wait_parity_cluster(hbar, t & 1);
            for (int i = tid - 320; i < 512; i += 192) {
                int b = i >> 6, o = (i & 63) * 2;
                __half2 hv = __floats2half2_rn(sm->h_s[wbuf][b][o], sm->h_s[wbuf][b][o + 1]);
                *(__half2*)&sm->xh[b * 520 + 384 + o] = hv;
            }
        }
        // SYNC_D needed only when the tree pipeline reads xh h-cols this step;
        // on shift steps next SYNC_A provides the ordering. anyr is block-uniform.
        if (anyr) {
            __syncthreads();   // SYNC_D

            // ---- P5: tree m2 (track) mma + store ----
            if (warp < 10) {
#pragma unroll
                for (int mm = 16; mm < 24; mm++) {
                    const unsigned k0 = (unsigned)(384 + (mm & 7) * 16);
                    unsigned a0, a1, a2, a3;
                    ldmatrix_x4(a0, a1, a2, a3, abase + k0 * 2u);
                    uint2 bfr = sm->gbs[(warp * 24 + mm) * 32 + lane];
                    mma16816(e0, e1, e2, e3, a0, a1, a2, a3, bfr.x, bfr.y);
                }
                const int row = lane >> 2, cc = (lane & 3) * 2;
                sm->pt[1024 + warp * 64 + row * 8 + cc]     = e0;
                sm->pt[1024 + warp * 64 + row * 8 + cc + 1] = e1;
            }
            __syncthreads();   // SYNC_E

            // ---- P6: compose -> red_s + stack stcg ----
            const int slotW = sp & 1;
            if (tid < 128) {
                const int jj = tid >> 3, b = tid & 7;
                if ((sm->trbits[b][w5] >> b5) & 1) {
                    const int j = (r << 4) + jj;
                    float gg[5];
#pragma unroll
                    for (int g = 0; g < 5; g++) {
                        int c = g * 16 + jj;
                        gg[g] = sm->pt[1024 + (c >> 3) * 64 + b * 8 + (c & 7)]
                              + sm->bias_red[c];
                    }
                    float cn = tanhf(gg[0]) * sigf(gg[1])
                             + sigf(gg[2]) * sm->s2v[b][128 + j]
                             + sigf(gg[3]) * sm->s1v[b][128 + j];
                    float v1 = cn;
                    float v0 = sigf(gg[4]) * tanhf(cn);
                    const int wp = sm->sch_wp[t][b];
                    __stcg(&stck[((size_t)b * Nn + wp) * 256 + j], v0);
                    __stcg(&stck[((size_t)b * Nn + wp) * 256 + 128 + j], v1);
                    sm->red_s[slotW][b][j]       = v0;
                    sm->red_s[slotW][b][128 + j] = v1;
                }
            }
            __syncthreads();   // SYNC_F

            // ---- P7: red publish + sbar arrive (publisher warps) ----
            if (isPub) {
#pragma unroll
                for (int rr = 0; rr < 4; rr++) {
                    int u = lane + rr * 32;
                    int half = u >> 6, b = (u >> 3) & 7, o = (u & 7) * 2;
                    float2 rv = *(const float2*)&sm->red_s[slotW][b][half * 128 + (r << 4) + o];
                    unsigned la = redbase + (unsigned)(((slotW * GPB + b) * 256
                                   + half * 128 + (r << 4) + o) * 4);
                    st_remote_b64(la, peer, rv.x, rv.y);
                }
                arrive_peer_rel(sbar, peer);
            }
        }
        prevAny = anyr;
    }

    fence_cluster();
    asm volatile("barrier.cluster.arrive.aligned;" ::: "memory");
    asm volatile("barrier.cluster.wait.aligned;"   ::: "memory");

    // final step's loss
    if (warp == 15) {
        const int wb_last = 1 - ((Tt - 1) & 1);
        float p0 = 0.f, p1 = 0.f;
#pragma unroll
        for (int m = 0; m < 4; m++) {
            int j = lane + 32 * m;
            float h = sm->h_s[wb_last][r][j];
            p0 += h * sm->wtrans[2 * j];
            p1 += h * sm->wtrans[2 * j + 1];
        }
#pragma unroll
        for (int off = 16; off > 0; off >>= 1) {
            p0 += __shfl_xor_sync(0xffffffffu, p0, off);
            p1 += __shfl_xor_sync(0xffffffffu, p1, off);
        }
        if (lane == 0) {
            float l0 = p0 + sm->btr[0], l1 = p1 + sm->btr[1];
            float m = fmaxf(l0, l1);
            float lse = m + logf(expf(l0 - m) + expf(l1 - m));
            int trp = (sm->trbits[r][(Tt - 1) >> 5] >> ((Tt - 1) & 31)) & 1;
            loss_reg += lse - ((trp == 0) ? l0 : l1);
            g_loss[b0 + r] = loss_reg;
        }
    }

    if (tid < 64) {
        int fin = sm->fin_ptr[r];
        float4 v = __ldcg((const float4*)&stck[((size_t)r * Nn + fin) * 256 + tid * 4]);
        *(float4*)&out_final[(size_t)(b0 + r) * 256 + tid * 4] = v;
    }
}

// ---------------------------------------------------------------------------
// Kernel 3: loss reduction
// ---------------------------------------------------------------------------
__global__ void loss_kernel(float* __restrict__ out, int loss_idx)
{
    __shared__ float sl[128];
    int tid = threadIdx.x;
    sl[tid] = g_loss[tid];
    __syncthreads();
    for (int off = 64; off > 0; off >>= 1) {
        if (tid < off) sl[tid] += sl[tid + off];
        __syncthreads();
    }
    if (tid == 0) out[loss_idx] = sl[0] / (float)(Tt * Bb);
}

// ---------------------------------------------------------------------------
extern "C" void kernel_launch(void* const* d_in, const int* in_sizes, int n_in,
                              void* d_out, int out_size)
{
    const int*   tokens      = (const int*)  d_in[0];
    const int*   transitions = (const int*)  d_in[1];
    const float* embed_table = (const float*)d_in[2];
    const float* W_proj      = (const float*)d_in[3];
    const float* W_buf       = (const float*)d_in[4];
    const float* W_s1        = (const float*)d_in[5];
    const float* W_s2        = (const float*)d_in[6];
    const float* W_lat       = (const float*)d_in[7];
    const float* b_lat       = (const float*)d_in[8];
    const float* W_trans     = (const float*)d_in[9];
    const float* b_trans     = (const float*)d_in[10];
    const float* W_left      = (const float*)d_in[11];
    const float* W_right     = (const float*)d_in[12];
    const float* W_track     = (const float*)d_in[13];
    const float* b_reduce    = (const float*)d_in[14];
    float* out = (float*)d_out;

    static bool attr_done = false;
    if (!attr_done) {
        cudaFuncSetAttribute(spinn_seq,
                             cudaFuncAttributeMaxDynamicSharedMemorySize,
                             (int)sizeof(Smem));
        attr_done = true;
    }

    embed_kernel<<<(Bb * Nn) / ETOK, 256>>>(tokens, embed_table, W_proj);
    spinn_seq<<<Bb, NT, sizeof(Smem)>>>(transitions,
                                        W_buf, W_s1, W_s2, W_lat, b_lat,
                                        W_trans, b_trans,
                                        W_left, W_right, W_track, b_reduce,
                                        out);
    loss_kernel<<<1, 128>>>(out, out_size - 1);
}

// round 16
// speedup vs baseline: 1.4245x; 1.2152x over previous
#include <cuda_runtime.h>
#include <cuda_fp16.h>
#include <math.h>

#define Bb 128
#define Nn 128
#define Ee 300
#define Tt 255
#define CSZ 8
#define GPB 8
#define NT 512

__device__ float g_buffer[Bb * Nn * 256];
__device__ float g_stack [Bb * Nn * 256];
__device__ float g_loss  [Bb];

// fast sigmoid/tanh via MUFU-backed __expf / __fdividef (error ~few ulp)
__device__ __forceinline__ float sigf(float x) {
    return __fdividef(1.0f, 1.0f + __expf(-x));
}
__device__ __forceinline__ float tanhfast(float x) {
    float t = __expf(-2.0f * fabsf(x));          // t in (0,1], never inf
    float r = __fdividef(1.0f - t, 1.0f + t);
    return copysignf(r, x);
}

__device__ __forceinline__ unsigned smem_u32(const void* p) {
    unsigned a;
    asm("{ .reg .u64 t; cvta.to.shared.u64 t, %1; cvt.u32.u64 %0, t; }" : "=r"(a) : "l"(p));
    return a;
}
__device__ __forceinline__ void fence_cluster() {
    asm volatile("fence.acq_rel.cluster;" ::: "memory");
}
__device__ __forceinline__ void arrive_peer_rel(unsigned la, int p) {
    asm volatile("{ .reg .b32 ra; mapa.shared::cluster.u32 ra, %0, %1;"
                 " mbarrier.arrive.release.cluster.shared::cluster.b64 _, [ra]; }"
                 :: "r"(la), "r"(p) : "memory");
}
__device__ __forceinline__ void wait_parity_cluster(unsigned a, unsigned par) {
    asm volatile("{ .reg .pred P;\n"
                 "W_%=:\n"
                 " mbarrier.try_wait.parity.acquire.cluster.shared::cta.b64 P, [%0], %1, 0x989680;\n"
                 " @P bra D_%=;\n"
                 " bra W_%=;\n"
                 "D_%=:\n}"
                 :: "r"(a), "r"(par) : "memory");
}
__device__ __forceinline__ void st_remote_b64(unsigned la, int p, float x, float y) {
    unsigned long long v = ((unsigned long long)__float_as_uint(y) << 32)
                         | (unsigned long long)__float_as_uint(x);
    asm volatile("{ .reg .b32 ra; mapa.shared::cluster.u32 ra, %0, %1;"
                 " st.shared::cluster.b64 [ra], %2; }"
                 :: "r"(la), "r"(p), "l"(v) : "memory");
}
__device__ __forceinline__ void ldmatrix_x4(unsigned& a0, unsigned& a1,
                                            unsigned& a2, unsigned& a3, unsigned addr) {
    asm volatile("ldmatrix.sync.aligned.m8n8.x4.shared.b16 {%0,%1,%2,%3}, [%4];"
                 : "=r"(a0), "=r"(a1), "=r"(a2), "=r"(a3) : "r"(addr));
}
__device__ __forceinline__ void mma16816(float& d0, float& d1, float& d2, float& d3,
                                         unsigned a0, unsigned a1, unsigned a2, unsigned a3,
                                         unsigned b0, unsigned b1) {
    asm volatile("mma.sync.aligned.m16n8k16.row.col.f32.f16.f16.f32 "
                 "{%0,%1,%2,%3}, {%4,%5,%6,%7}, {%8,%9}, {%0,%1,%2,%3};"
                 : "+f"(d0), "+f"(d1), "+f"(d2), "+f"(d3)
                 : "r"(a0), "r"(a1), "r"(a2), "r"(a3), "r"(b0), "r"(b1));
}
__device__ __forceinline__ unsigned pack_h2(float a, float b) {
    __half2 h = __floats2half2_rn(a, b);
    return *(unsigned*)&h;
}

// ---------------------------------------------------------------------------
// Kernel 1: buffer[b,n,:] = embed_table[tokens[b,n]] @ W_proj  (ETOK=8)
// ---------------------------------------------------------------------------
#define ETOK 8
__global__ void __launch_bounds__(256) embed_kernel(
    const int*   __restrict__ tokens,
    const float* __restrict__ embed_table,
    const float* __restrict__ W_proj)
{
    __shared__ __align__(16) float se[ETOK * Ee];
    __shared__ int stok[ETOK];
    const int blk = blockIdx.x;
    const int tid = threadIdx.x;

    if (tid < ETOK) stok[tid] = tokens[blk * ETOK + tid];
    __syncthreads();
    for (int idx = tid; idx < ETOK * Ee; idx += 256) {
        int j = idx / Ee, e = idx - j * Ee;
        se[idx] = embed_table[(size_t)stok[j] * Ee + e];
    }
    __syncthreads();

    const int col = tid;
    float acc[ETOK];
#pragma unroll
    for (int j = 0; j < ETOK; j++) acc[j] = 0.0f;
    for (int e = 0; e < Ee; e += 4) {
        float w0 = W_proj[(e + 0) * 256 + col];
        float w1 = W_proj[(e + 1) * 256 + col];
        float w2 = W_proj[(e + 2) * 256 + col];
        float w3 = W_proj[(e + 3) * 256 + col];
#pragma unroll
        for (int j = 0; j < ETOK; j++) {
            float4 s = *(const float4*)&se[j * Ee + e];
            acc[j] += s.x * w0 + s.y * w1 + s.z * w2 + s.w * w3;
        }
    }
#pragma unroll
    for (int j = 0; j < ETOK; j++)
        g_buffer[(size_t)(blk * ETOK + j) * 256 + col] = acc[j];
}

// ---------------------------------------------------------------------------
// Kernel 2: clustered scan (R12 structure, fast transcendentals)
// ---------------------------------------------------------------------------
struct __align__(16) Smem {
    float h_s[2][GPB][128];
    float bt[GPB][256];
    float s1v[GPB][256];
    float s2v[GPB][256];
    float red_s[2][GPB][256];
    float pt[1664];                 // tracker 16*64 | tree at 1024: 10*64
    float c_s[GPB][16];
    float bias_lat[64];
    float bias_red[80];
    float wtrans[256];
    float btr[2];
    int   fin_ptr[GPB];
    unsigned long long mbar[2];     // [0]=hbar, [1]=sbar (count 224)
    __align__(16) __half xh[16 * 520];
    uint2 gbs[10 * 24 * 32];
    unsigned trbits[GPB][8];
    unsigned char sch_wp[Tt][GPB];
    unsigned char sch_bt[Tt + 1][GPB];
    signed char   sch_rf[Tt][GPB];
};

__global__ void __launch_bounds__(NT, 1) __cluster_dims__(CSZ, 1, 1)
spinn_seq(
    const int*   __restrict__ transitions,
    const float* __restrict__ W_buf,  const float* __restrict__ W_s1,
    const float* __restrict__ W_s2,   const float* __restrict__ W_lat,
    const float* __restrict__ b_lat,
    const float* __restrict__ W_trans,const float* __restrict__ b_trans,
    const float* __restrict__ W_left, const float* __restrict__ W_right,
    const float* __restrict__ W_track,const float* __restrict__ b_reduce,
    float* __restrict__ out_final)
{
    extern __shared__ char smraw[];
    Smem* sm = (Smem*)smraw;
    const int tid  = threadIdx.x;
    const int warp = tid >> 5;
    const int lane = tid & 31;
    const int r    = blockIdx.x & (CSZ - 1);
    const int b0   = blockIdx.x & ~(CSZ - 1);

    float*       stck = g_stack  + (size_t)b0 * Nn * 256;
    const float* buf  = g_buffer + (size_t)b0 * Nn * 256;

    // ---------------- init: tracker B fragments in registers ----------------
    unsigned tb0[16], tb1[16];
    {
        const int nt = warp & 7, kh = warp >> 3;
        const int cl = nt * 8 + (lane >> 2);
        const int G  = ((cl >> 4) << 7) + (r << 4) + (cl & 15);
#pragma unroll
        for (int mm = 0; mm < 16; mm++) {
            int kb = (kh * 16 + mm) * 16 + (lane & 3) * 2;
            float w00, w01, w10, w11;
            {
                int k = kb;
                w00 = (k < 128) ? W_buf[k * 512 + G] : (k < 256) ? W_s1[(k - 128) * 512 + G]
                    : (k < 384) ? W_s2[(k - 256) * 512 + G] : W_lat[(k - 384) * 512 + G];
                k = kb + 1;
                w01 = (k < 128) ? W_buf[k * 512 + G] : (k < 256) ? W_s1[(k - 128) * 512 + G]
                    : (k < 384) ? W_s2[(k - 256) * 512 + G] : W_lat[(k - 384) * 512 + G];
                k = kb + 8;
                w10 = (k < 128) ? W_buf[k * 512 + G] : (k < 256) ? W_s1[(k - 128) * 512 + G]
                    : (k < 384) ? W_s2[(k - 256) * 512 + G] : W_lat[(k - 384) * 512 + G];
                k = kb + 9;
                w11 = (k < 128) ? W_buf[k * 512 + G] : (k < 256) ? W_s1[(k - 128) * 512 + G]
                    : (k < 384) ? W_s2[(k - 256) * 512 + G] : W_lat[(k - 384) * 512 + G];
            }
            tb0[mm] = pack_h2(w00, w01);
            tb1[mm] = pack_h2(w10, w11);
        }
    }
    if (warp < 10) {
        const int cl = warp * 8 + (lane >> 2);
        const int G  = ((cl >> 4) << 7) + (r << 4) + (cl & 15);
        for (int mm = 0; mm < 24; mm++) {
            int m  = mm >> 3;
            int kk = (mm & 7) * 16 + (lane & 3) * 2;
            const float* W = (m == 0) ? W_left : (m == 1) ? W_right : W_track;
            uint2 v;
            v.x = pack_h2(W[kk * 640 + G],       W[(kk + 1) * 640 + G]);
            v.y = pack_h2(W[(kk + 8) * 640 + G], W[(kk + 9) * 640 + G]);
            sm->gbs[(warp * 24 + mm) * 32 + lane] = v;
        }
    }
    if (tid < 64) sm->bias_lat[tid] = b_lat[((tid >> 4) << 7) + (r << 4) + (tid & 15)];
    if (tid < 80) sm->bias_red[tid] = b_reduce[((tid >> 4) << 7) + (r << 4) + (tid & 15)];
    if (tid < 256) sm->wtrans[tid] = W_trans[tid];
    if (tid < 2) sm->btr[tid] = b_trans[tid];
    if (tid < 64) {
        int g = tid >> 3, w = tid & 7;
        unsigned bits = 0;
        for (int i = 0; i < 32; i++) {
            int tt = w * 32 + i;
            if (tt < Tt) bits |= (unsigned)(transitions[(b0 + g) * Tt + tt] & 1) << i;
        }
        sm->trbits[g][w] = bits;
    }
    for (int i = tid; i < 2 * GPB * 128; i += NT) ((float*)sm->h_s)[i] = 0.f;
    for (int i = tid; i < GPB * 16;  i += NT) ((float*)sm->c_s)[i] = 0.f;
    for (int i = tid; i < GPB * 256; i += NT) {
        ((float*)sm->s1v)[i] = 0.f;
        ((float*)sm->s2v)[i] = 0.f;
    }
    for (int i = tid; i < 2 * GPB * 256; i += NT) ((float*)sm->red_s)[i] = 0.f;
    for (int i = tid; i < 16 * 520; i += NT) sm->xh[i] = __float2half(0.f);
    for (int i = tid; i < GPB * 64; i += NT) {
        int b = i >> 6, q = (i & 63) * 4;
        *(float4*)&sm->bt[b][q] = *(const float4*)&buf[((size_t)b * Nn) * 256 + q];
    }
    if (tid == 0) {
        unsigned mb = smem_u32(&sm->mbar[0]);
        asm volatile("mbarrier.init.shared.b64 [%0], %1;" :: "r"(mb),   "r"(224) : "memory");
        asm volatile("mbarrier.init.shared.b64 [%0], %1;" :: "r"(mb+8), "r"(224) : "memory");
    }
    __syncthreads();

    if (tid < GPB) {
        const int g = tid;
        int p = 0, bp = 0;
        for (int t = 0; t < Tt; t++) {
            int trv = (sm->trbits[g][t >> 5] >> (t & 31)) & 1;
            int bi = (bp < Nn - 1) ? bp : (Nn - 1);
            sm->sch_bt[t][g] = (unsigned char)bi;
            int wp = trv ? ((p - 2 >= 0) ? p - 2 : 0) : p;
            if (wp > Nn - 1) wp = Nn - 1;
            sm->sch_wp[t][g] = (unsigned char)wp;
            sm->sch_rf[t][g] = (signed char)((trv && p >= 3) ? (p - 3) : -1);
            p  += trv ? -1 : 1;
            bp += trv ? 0 : 1;
        }
        sm->sch_bt[Tt][g] = sm->sch_bt[Tt - 1][g];
        int fin = (p - 1 >= 0) ? p - 1 : 0;
        sm->fin_ptr[g] = (fin > Nn - 1) ? Nn - 1 : fin;
    }
    __syncthreads();
    asm volatile("barrier.cluster.arrive.aligned;" ::: "memory");
    asm volatile("barrier.cluster.wait.aligned;"   ::: "memory");

    const unsigned hbar    = smem_u32(&sm->mbar[0]);
    const unsigned sbar    = hbar + 8;
    const unsigned hsbase  = smem_u32(&sm->h_s[0][0][0]);
    const unsigned redbase = smem_u32(&sm->red_s[0][0][0]);
    const unsigned xhbase  = smem_u32(&sm->xh[0]);

    const unsigned lrow  = lane & 15;
    const unsigned lcolb = (lane & 16) >> 1;
    const unsigned abase = xhbase + (lrow * 520u + lcolb) * 2u;

    const int rb_ = tid >> 6;               // rename batch owner
    const int rd  = (tid & 63) * 4;         // 4-float chunk of 256
    const int isPub = (warp >= 9);
    const int pw    = warp - 9;
    const int peer  = pw + (pw >= r ? 1 : 0);

    const float4 z4 = make_float4(0.f, 0.f, 0.f, 0.f);
    float4 rfa = z4, bna = z4;
    float loss_reg = 0.f;
    int sp = 0;
    int prevAny = 0;

    for (int t = 0; t < Tt; t++) {
        const int w5 = t >> 5, b5 = t & 31;
        const int rb = t & 1, wbuf = 1 - rb;

        unsigned anyr = 0;
#pragma unroll
        for (int g = 0; g < GPB; g++) anyr |= (sm->trbits[g][w5] >> b5) & 1u;

        // ======== P0 (fused): sbar wait + rename + xh fill + stack write + prefetch
        const int slot = sp & 1;
        if (prevAny) { wait_parity_cluster(sbar, slot); sp++; }
        {
            float4 bt_v = *(const float4*)&sm->bt[rb_][rd];
            float4 s1_v = *(const float4*)&sm->s1v[rb_][rd];
            float4 s2_v = *(const float4*)&sm->s2v[rb_][rd];
            if (t > 0) {
                if ((sm->trbits[rb_][(t - 1) >> 5] >> ((t - 1) & 31)) & 1) {
                    s1_v = *(const float4*)&sm->red_s[slot][rb_][rd];
                    s2_v = rfa;
                } else {
                    s2_v = s1_v; s1_v = bt_v; bt_v = bna;
                }
                *(float4*)&sm->bt[rb_][rd]  = bt_v;
                *(float4*)&sm->s1v[rb_][rd] = s1_v;
                *(float4*)&sm->s2v[rb_][rd] = s2_v;
            }
            if (rd < 128) {
                uint2 v;
                v.x = pack_h2(bt_v.x, bt_v.y); v.y = pack_h2(bt_v.z, bt_v.w);
                *(uint2*)&sm->xh[rb_ * 520 + rd] = v;
                v.x = pack_h2(s1_v.x, s1_v.y); v.y = pack_h2(s1_v.z, s1_v.w);
                *(uint2*)&sm->xh[rb_ * 520 + 128 + rd] = v;
                v.x = pack_h2(s2_v.x, s2_v.y); v.y = pack_h2(s2_v.z, s2_v.w);
                *(uint2*)&sm->xh[rb_ * 520 + 256 + rd] = v;
            }
            if ((((sm->trbits[rb_][w5] >> b5) & 1) == 0) && ((rd >> 5) == r)) {
                const int wp = sm->sch_wp[t][rb_];
                __stcg((float4*)&stck[((size_t)rb_ * Nn + wp) * 256 + rd], bt_v);
            }
            int nbt = sm->sch_bt[t + 1][rb_];
            bna = __ldg((const float4*)&buf[((size_t)rb_ * Nn + nbt) * 256 + rd]);
            int rfi = sm->sch_rf[t][rb_];
            rfa = (rfi >= 0)
                ? __ldcg((const float4*)&stck[((size_t)rb_ * Nn + rfi) * 256 + rd])
                : z4;
        }
        __syncthreads();   // SYNC_A

        // ======== P1: tracker mma (16 warps) + lazy loss (warp 15)
        {
            float d0 = 0.f, d1 = 0.f, d2 = 0.f, d3 = 0.f;
#pragma unroll
            for (int mm = 0; mm < 16; mm++) {
                const unsigned k0 = ((unsigned)((warp >> 3) * 16 + mm)) * 16u;
                unsigned a0, a1, a2, a3;
                ldmatrix_x4(a0, a1, a2, a3, abase + k0 * 2u);
                mma16816(d0, d1, d2, d3, a0, a1, a2, a3, tb0[mm], tb1[mm]);
            }
            const int row = lane >> 2, cc = (lane & 3) * 2;
            sm->pt[warp * 64 + row * 8 + cc]     = d0;
            sm->pt[warp * 64 + row * 8 + cc + 1] = d1;
        }
        if (t > 0 && warp == 15) {
            float p0 = 0.f, p1 = 0.f;
#pragma unroll
            for (int m = 0; m < 4; m++) {
                int j = lane + 32 * m;
                float h = sm->h_s[rb][r][j];
                p0 += h * sm->wtrans[2 * j];
                p1 += h * sm->wtrans[2 * j + 1];
            }
#pragma unroll
            for (int off = 16; off > 0; off >>= 1) {
                p0 += __shfl_xor_sync(0xffffffffu, p0, off);
                p1 += __shfl_xor_sync(0xffffffffu, p1, off);
            }
            if (lane == 0) {
                float l0 = p0 + sm->btr[0], l1 = p1 + sm->btr[1];
                float m = fmaxf(l0, l1);
                float lse = m + logf(expf(l0 - m) + expf(l1 - m));
                int trp = (sm->trbits[r][(t - 1) >> 5] >> ((t - 1) & 31)) & 1;
                loss_reg += lse - ((trp == 0) ? l0 : l1);
            }
        }
        __syncthreads();   // SYNC_B

        // ======== P2: cell update -> h_s[wbuf], c_s  (fast transcendentals)
        if (tid < 128) {
            const int jj = tid >> 3, b = tid & 7;
            float ga[4];
#pragma unroll
            for (int g = 0; g < 4; g++) {
                int c = g * 16 + jj;
                int u0 = (c >> 3), u1 = 8 + (c >> 3), o = b * 8 + (c & 7);
                float v = sm->pt[u0 * 64 + o] + sm->pt[u1 * 64 + o];
                if (t > 0) v += sm->bias_lat[c];
                ga[g] = v;
            }
            float cn = sigf(ga[2]) * sm->c_s[b][jj] + sigf(ga[1]) * tanhfast(ga[0]);
            float hn = sigf(ga[3]) * tanhfast(cn);
            sm->c_s[b][jj] = cn;
            sm->h_s[wbuf][b][(r << 4) + jj] = hn;
        }
        __syncthreads();   // SYNC_C

        // ======== P3: h publish (warps 9-15) || tree L/R mma (warps 0-9)
        float e0 = 0.f, e1 = 0.f, e2 = 0.f, e3 = 0.f;
        if (isPub) {
#pragma unroll
            for (int rr = 0; rr < 2; rr++) {
                int u = lane + rr * 32;
                int b = u >> 3, o = (u & 7) * 2;
                float2 hv = *(const float2*)&sm->h_s[wbuf][b][(r << 4) + o];
                unsigned la = hsbase + (unsigned)(((wbuf * GPB + b) * 128 + (r << 4) + o) * 4);
                st_remote_b64(la, peer, hv.x, hv.y);
            }
            arrive_peer_rel(hbar, peer);
        }
        if (anyr && warp < 10) {
#pragma unroll
            for (int mm = 0; mm < 16; mm++) {
                const unsigned k0 = (unsigned)(((mm >> 3) ? 128 : 256) + (mm & 7) * 16);
                unsigned a0, a1, a2, a3;
                ldmatrix_x4(a0, a1, a2, a3, abase + k0 * 2u);
                uint2 bfr = sm->gbs[(warp * 24 + mm) * 32 + lane];
                mma16816(e0, e1, e2, e3, a0, a1, a2, a3, bfr.x, bfr.y);
            }
        }

        // ======== P4: warps 10-15 wait hbar(t) + fill xh h-cols
        if (warp >= 10) {
            wait_parity_cluster(hbar, t & 1);
            for (int i = tid - 320; i < 512; i += 192) {
                int b = i >> 6, o = (i & 63) * 2;
                __half2 hv = __floats2half2_rn(sm->h_s[wbuf][b][o], sm->h_s[wbuf][b][o + 1]);
                *(__half2*)&sm->xh[b * 520 + 384 + o] = hv;
            }
        }
        __syncthreads();   // SYNC_D (unconditional — R14 showed the skip hurts)

        if (anyr) {
            // ---- P5: tree m2 (track) mma + store ----
            if (warp < 10) {
#pragma unroll
                for (int mm = 16; mm < 24; mm++) {
                    const unsigned k0 = (unsigned)(384 + (mm & 7) * 16);
                    unsigned a0, a1, a2, a3;
                    ldmatrix_x4(a0, a1, a2, a3, abase + k0 * 2u);
                    uint2 bfr = sm->gbs[(warp * 24 + mm) * 32 + lane];
                    mma16816(e0, e1, e2, e3, a0, a1, a2, a3, bfr.x, bfr.y);
                }
                const int row = lane >> 2, cc = (lane & 3) * 2;
                sm->pt[1024 + warp * 64 + row * 8 + cc]     = e0;
                sm->pt[1024 + warp * 64 + row * 8 + cc + 1] = e1;
            }
            __syncthreads();   // SYNC_E

            // ---- P6: compose -> red_s + stack stcg (fast transcendentals) ----
            const int slotW = sp & 1;
            if (tid < 128) {
                const int jj = tid >> 3, b = tid & 7;
                if ((sm->trbits[b][w5] >> b5) & 1) {
                    const int j = (r << 4) + jj;
                    float gg[5];
#pragma unroll
                    for (int g = 0; g < 5; g++) {
                        int c = g * 16 + jj;
                        gg[g] = sm->pt[1024 + (c >> 3) * 64 + b * 8 + (c & 7)]
                              + sm->bias_red[c];
                    }
                    float cn = tanhfast(gg[0]) * sigf(gg[1])
                             + sigf(gg[2]) * sm->s2v[b][128 + j]
                             + sigf(gg[3]) * sm->s1v[b][128 + j];
                    float v1 = cn;
                    float v0 = sigf(gg[4]) * tanhfast(cn);
                    const int wp = sm->sch_wp[t][b];
                    __stcg(&stck[((size_t)b * Nn + wp) * 256 + j], v0);
                    __stcg(&stck[((size_t)b * Nn + wp) * 256 + 128 + j], v1);
                    sm->red_s[slotW][b][j]       = v0;
                    sm->red_s[slotW][b][128 + j] = v1;
                }
            }
            __syncthreads();   // SYNC_F

            // ---- P7: red publish + sbar arrive (publisher warps) ----
            if (isPub) {
#pragma unroll
                for (int rr = 0; rr < 4; rr++) {
                    int u = lane + rr * 32;
                    int half = u >> 6, b = (u >> 3) & 7, o = (u & 7) * 2;
                    float2 rv = *(const float2*)&sm->red_s[slotW][b][half * 128 + (r << 4) + o];
                    unsigned la = redbase + (unsigned)(((slotW * GPB + b) * 256
                                   + half * 128 + (r << 4) + o) * 4);
                    st_remote_b64(la, peer, rv.x, rv.y);
                }
                arrive_peer_rel(sbar, peer);
            }
        }
        prevAny = anyr;
    }

    fence_cluster();
    asm volatile("barrier.cluster.arrive.aligned;" ::: "memory");
    asm volatile("barrier.cluster.wait.aligned;"   ::: "memory");

    // final step's loss
    if (warp == 15) {
        const int wb_last = 1 - ((Tt - 1) & 1);
        float p0 = 0.f, p1 = 0.f;
#pragma unroll
        for (int m = 0; m < 4; m++) {
            int j = lane + 32 * m;
            float h = sm->h_s[wb_last][r][j];
            p0 += h * sm->wtrans[2 * j];
            p1 += h * sm->wtrans[2 * j + 1];
        }
#pragma unroll
        for (int off = 16; off > 0; off >>= 1) {
            p0 += __shfl_xor_sync(0xffffffffu, p0, off);
            p1 += __shfl_xor_sync(0xffffffffu, p1, off);
        }
        if (lane == 0) {
            float l0 = p0 + sm->btr[0], l1 = p1 + sm->btr[1];
            float m = fmaxf(l0, l1);
            float lse = m + logf(expf(l0 - m) + expf(l1 - m));
            int trp = (sm->trbits[r][(Tt - 1) >> 5] >> ((Tt - 1) & 31)) & 1;
            loss_reg += lse - ((trp == 0) ? l0 : l1);
            g_loss[b0 + r] = loss_reg;
        }
    }

    if (tid < 64) {
        int fin = sm->fin_ptr[r];
        float4 v = __ldcg((const float4*)&stck[((size_t)r * Nn + fin) * 256 + tid * 4]);
        *(float4*)&out_final[(size_t)(b0 + r) * 256 + tid * 4] = v;
    }
}

// ---------------------------------------------------------------------------
// Kernel 3: loss reduction
// ---------------------------------------------------------------------------
__global__ void loss_kernel(float* __restrict__ out, int loss_idx)
{
    __shared__ float sl[128];
    int tid = threadIdx.x;
    sl[tid] = g_loss[tid];
    __syncthreads();
    for (int off = 64; off > 0; off >>= 1) {
        if (tid < off) sl[tid] += sl[tid + off];
        __syncthreads();
    }
    if (tid == 0) out[loss_idx] = sl[0] / (float)(Tt * Bb);
}

// ---------------------------------------------------------------------------
extern "C" void kernel_launch(void* const* d_in, const int* in_sizes, int n_in,
                              void* d_out, int out_size)
{
    const int*   tokens      = (const int*)  d_in[0];
    const int*   transitions = (const int*)  d_in[1];
    const float* embed_table = (const float*)d_in[2];
    const float* W_proj      = (const float*)d_in[3];
    const float* W_buf       = (const float*)d_in[4];
    const float* W_s1        = (const float*)d_in[5];
    const float* W_s2        = (const float*)d_in[6];
    const float* W_lat       = (const float*)d_in[7];
    const float* b_lat       = (const float*)d_in[8];
    const float* W_trans     = (const float*)d_in[9];
    const float* b_trans     = (const float*)d_in[10];
    const float* W_left      = (const float*)d_in[11];
    const float* W_right     = (const float*)d_in[12];
    const float* W_track     = (const float*)d_in[13];
    const float* b_reduce    = (const float*)d_in[14];
    float* out = (float*)d_out;

    static bool attr_done = false;
    if (!attr_done) {
        cudaFuncSetAttribute(spinn_seq,
                             cudaFuncAttributeMaxDynamicSharedMemorySize,
                             (int)sizeof(Smem));
        attr_done = true;
    }

    embed_kernel<<<(Bb * Nn) / ETOK, 256>>>(tokens, embed_table, W_proj);
    spinn_seq<<<Bb, NT, sizeof(Smem)>>>(transitions,
                                        W_buf, W_s1, W_s2, W_lat, b_lat,
                                        W_trans, b_trans,
                                        W_left, W_right, W_track, b_reduce,
                                        out);
    loss_kernel<<<1, 128>>>(out, out_size - 1);
}